// round 1
// baseline (speedup 1.0000x reference)
#include <cuda_runtime.h>
#include <math.h>

#define NN 50000
#define EE 800000
#define HH 128
#define GG 128
#define CC 10
#define BM 64

// ---------------- static device scratch (no allocations allowed) ----------------
__device__ int   g_deg[NN];
__device__ int   g_starts[NN + 1];
__device__ int   g_cursor[NN];
__device__ int   g_src[EE];
__device__ float g_dinv[NN];
__device__ float g_bufA[(size_t)NN * HH];
__device__ float g_bufB[(size_t)NN * HH];
__device__ float g_pool[GG * HH];
__device__ float g_cnt[GG];

__device__ __forceinline__ float* dev_buf(int s) { return s == 1 ? g_bufA : g_bufB; }

// ---------------- graph preprocessing ----------------
__global__ void k_zero_deg() {
    int i = blockIdx.x * blockDim.x + threadIdx.x;
    if (i < NN) g_deg[i] = 0;
}

__global__ void k_deg(const int* __restrict__ col) {
    int e = blockIdx.x * blockDim.x + threadIdx.x;
    if (e < EE) atomicAdd(&g_deg[col[e]], 1);
}

// single-block exclusive scan of g_deg -> g_starts (N=50000, 1024 threads)
__global__ void k_scan() {
    __shared__ int warp_sums[32];
    __shared__ int carry_s;
    int tid = threadIdx.x;
    int lane = tid & 31, wid = tid >> 5;
    if (tid == 0) carry_s = 0;
    __syncthreads();
    for (int base = 0; base < NN; base += 1024) {
        int i = base + tid;
        int v = (i < NN) ? g_deg[i] : 0;
        int s = v;
        #pragma unroll
        for (int o = 1; o < 32; o <<= 1) {
            int t = __shfl_up_sync(0xFFFFFFFFu, s, o);
            if (lane >= o) s += t;
        }
        if (lane == 31) warp_sums[wid] = s;
        __syncthreads();
        if (wid == 0) {
            int ws = warp_sums[lane];
            #pragma unroll
            for (int o = 1; o < 32; o <<= 1) {
                int t = __shfl_up_sync(0xFFFFFFFFu, ws, o);
                if (lane >= o) ws += t;
            }
            warp_sums[lane] = ws;
        }
        __syncthreads();
        int offset = (wid > 0) ? warp_sums[wid - 1] : 0;
        int incl = s + offset;
        int carry = carry_s;
        if (i < NN) g_starts[i] = carry + incl - v;  // exclusive
        __syncthreads();
        if (tid == 1023) carry_s = carry + incl;
        __syncthreads();
    }
    if (tid == 0) g_starts[NN] = carry_s;
}

__global__ void k_dinv_cursor() {
    int i = blockIdx.x * blockDim.x + threadIdx.x;
    if (i < NN) {
        g_dinv[i] = rsqrtf((float)(g_deg[i] + 1));  // +1 self loop
        g_cursor[i] = g_starts[i];
    }
}

__global__ void k_fill(const int* __restrict__ row, const int* __restrict__ col) {
    int e = blockIdx.x * blockDim.x + threadIdx.x;
    if (e < EE) {
        int c = col[e];
        int p = atomicAdd(&g_cursor[c], 1);
        g_src[p] = row[e];
    }
}

// ---------------- aggregation (warp per node, float4 lanes) ----------------
__global__ void k_agg1(const float4* __restrict__ x4) {
    int node = blockIdx.x * 8 + (threadIdx.x >> 5);
    if (node >= NN) return;
    int lane = threadIdx.x & 31;
    float4 acc = make_float4(0.f, 0.f, 0.f, 0.f);
    int s = g_starts[node], e = g_starts[node + 1];
    for (int j = s; j < e; j++) {
        int u = g_src[j];
        float4 v = __ldg(&x4[(size_t)u * 32 + lane]);
        acc.x += v.x; acc.y += v.y; acc.z += v.z; acc.w += v.w;
    }
    ((float4*)g_bufA)[(size_t)node * 32 + lane] = acc;
}

// out[i] = dinv[i]*(hq[i] + sum_src hq[src]) + b ; optional relu
__global__ void k_aggn(int in_sel, int out_sel, const float* __restrict__ bias, int relu) {
    int node = blockIdx.x * 8 + (threadIdx.x >> 5);
    if (node >= NN) return;
    int lane = threadIdx.x & 31;
    const float4* hq = (const float4*)dev_buf(in_sel);
    float4* outp = (float4*)dev_buf(out_sel);
    float4 acc = hq[(size_t)node * 32 + lane];  // self term
    int s = g_starts[node], e = g_starts[node + 1];
    for (int j = s; j < e; j++) {
        int u = g_src[j];
        float4 v = __ldg(&hq[(size_t)u * 32 + lane]);
        acc.x += v.x; acc.y += v.y; acc.z += v.z; acc.w += v.w;
    }
    float dv = g_dinv[node];
    float4 b = ((const float4*)bias)[lane];
    float4 r;
    r.x = fmaf(acc.x, dv, b.x);
    r.y = fmaf(acc.y, dv, b.y);
    r.z = fmaf(acc.z, dv, b.z);
    r.w = fmaf(acc.w, dv, b.w);
    if (relu) {
        r.x = fmaxf(r.x, 0.f); r.y = fmaxf(r.y, 0.f);
        r.z = fmaxf(r.z, 0.f); r.w = fmaxf(r.w, 0.f);
    }
    outp[(size_t)node * 32 + lane] = r;
}

// ---------------- GEMM: C[M,128] = A[M,128] @ W[128,128]^T  (C[m,n]=sum_k A[m,k]W[n,k]) ----------------
// flags: 1 = accumulate into existing C, 2 = relu, 4 = scale output row by g_dinv[m]
#define FL_ACC  1
#define FL_RELU 2
#define FL_DINV 4
#define GEMM_SMEM (128 * 129 * 4 + BM * 128 * 4)

__global__ void k_gemm(const float* __restrict__ A_ext, int a_sel, int c_sel,
                       const float* __restrict__ W,
                       const float* __restrict__ bias, int flags) {
    extern __shared__ float sm[];
    float* Wt = sm;               // [128][129] transposed W: Wt[k*129+n] = W[n,k]
    float* As = sm + 128 * 129;   // [BM][128]
    const float* A = a_sel ? dev_buf(a_sel) : A_ext;
    float* Cm = dev_buf(c_sel);
    int tid = threadIdx.x, lane = tid & 31, warp = tid >> 5;
    int m0 = blockIdx.x * BM;

    // load W transposed (coalesced reads, conflict-free pitch-129 writes)
    #pragma unroll
    for (int i = 0; i < 64; i++) {
        int idx = tid + i * 256;            // idx = n*128 + k
        int k = idx & 127, n = idx >> 7;
        Wt[k * 129 + n] = W[idx];
    }
    // load A tile (float4 coalesced), zero-fill tail
    const float4* A4 = (const float4*)A;
    float4* As4 = (float4*)As;
    #pragma unroll
    for (int i = 0; i < 8; i++) {
        int idx4 = tid + i * 256;           // 0..2047 (64 rows * 32 float4)
        int rrow = idx4 >> 5, cc = idx4 & 31;
        int m = m0 + rrow;
        float4 v = make_float4(0.f, 0.f, 0.f, 0.f);
        if (m < NN) v = __ldg(&A4[(size_t)m * 32 + cc]);
        As4[idx4] = v;
    }
    __syncthreads();

    float acc[8][4];
    #pragma unroll
    for (int i = 0; i < 8; i++)
        #pragma unroll
        for (int j = 0; j < 4; j++) acc[i][j] = 0.f;

    int r = warp * 8;
    #pragma unroll 4
    for (int k = 0; k < 128; k++) {
        float w0 = Wt[k * 129 + lane];
        float w1 = Wt[k * 129 + lane + 32];
        float w2 = Wt[k * 129 + lane + 64];
        float w3 = Wt[k * 129 + lane + 96];
        #pragma unroll
        for (int i = 0; i < 8; i++) {
            float a = As[(r + i) * 128 + k];
            acc[i][0] = fmaf(a, w0, acc[i][0]);
            acc[i][1] = fmaf(a, w1, acc[i][1]);
            acc[i][2] = fmaf(a, w2, acc[i][2]);
            acc[i][3] = fmaf(a, w3, acc[i][3]);
        }
    }

    #pragma unroll
    for (int i = 0; i < 8; i++) {
        int m = m0 + r + i;
        if (m >= NN) continue;
        float dv = (flags & FL_DINV) ? g_dinv[m] : 1.f;
        #pragma unroll
        for (int j = 0; j < 4; j++) {
            int c = lane + 32 * j;
            float v = acc[i][j];
            if (flags & FL_ACC) v += Cm[(size_t)m * 128 + c];
            if (bias) v += bias[c];
            if (flags & FL_DINV) v *= dv;
            if (flags & FL_RELU) v = fmaxf(v, 0.f);
            Cm[(size_t)m * 128 + c] = v;
        }
    }
}

// ---------------- pooling + normalize + classifier ----------------
__global__ void k_zero_pool() {
    int i = blockIdx.x * blockDim.x + threadIdx.x;
    if (i < GG * HH) g_pool[i] = 0.f;
    if (i < GG) g_cnt[i] = 0.f;
}

__global__ void k_pool(const int* __restrict__ batch, int h_sel) {
    const float* h = dev_buf(h_sel);
    int id = blockIdx.x * blockDim.x + threadIdx.x;
    if (id < NN * HH) {
        int node = id >> 7;
        atomicAdd(&g_pool[batch[node] * HH + (id & 127)], h[id]);
    }
}

__global__ void k_cnt(const int* __restrict__ batch) {
    int i = blockIdx.x * blockDim.x + threadIdx.x;
    if (i < NN) atomicAdd(&g_cnt[batch[i]], 1.f);
}

__global__ void k_final1(float* __restrict__ dout) {
    __shared__ float ws[4];
    int g = blockIdx.x, t = threadIdx.x;
    float c = fmaxf(g_cnt[g], 1.f);
    float v = g_pool[g * HH + t] / c;
    float s = v * v;
    #pragma unroll
    for (int o = 16; o > 0; o >>= 1) s += __shfl_down_sync(0xFFFFFFFFu, s, o);
    if ((t & 31) == 0) ws[t >> 5] = s;
    __syncthreads();
    float tot = ws[0] + ws[1] + ws[2] + ws[3];
    float nrm = fmaxf(sqrtf(tot), 1e-12f);
    dout[g * HH + t] = v / nrm;
}

__global__ void k_final2(const float* __restrict__ Wl, const float* __restrict__ bl,
                         float* __restrict__ dout) {
    __shared__ float xs[HH];
    __shared__ float winv[CC];
    int g = blockIdx.x, t = threadIdx.x;
    xs[t] = dout[g * HH + t];
    if (t < CC) {
        float s = 0.f;
        #pragma unroll 8
        for (int k = 0; k < HH; k++) { float w = Wl[t * HH + k]; s = fmaf(w, w, s); }
        winv[t] = 1.f / fmaxf(sqrtf(s), 1e-12f);
    }
    __syncthreads();
    if (t < CC) {
        float s = 0.f;
        #pragma unroll 8
        for (int k = 0; k < HH; k++) s = fmaf(xs[k], Wl[t * HH + k], s);
        dout[GG * HH + g * CC + t] = fmaf(s, winv[t], bl[t]);
    }
}

// ---------------- launch ----------------
extern "C" void kernel_launch(void* const* d_in, const int* in_sizes, int n_in,
                              void* d_out, int out_size) {
    const float* x    = (const float*)d_in[0];
    const int*   ei   = (const int*)d_in[1];
    const int*   batch= (const int*)d_in[2];
    const float* W1r  = (const float*)d_in[3];
    const float* b1   = (const float*)d_in[4];
    const float* W1x  = (const float*)d_in[5];
    const float* W2   = (const float*)d_in[6];
    const float* b2   = (const float*)d_in[7];
    const float* W3   = (const float*)d_in[8];
    const float* b3   = (const float*)d_in[9];
    const float* Wl   = (const float*)d_in[10];
    const float* bl   = (const float*)d_in[11];
    const int* row = ei;
    const int* col = ei + EE;
    float* out = (float*)d_out;

    cudaFuncSetAttribute(k_gemm, cudaFuncAttributeMaxDynamicSharedMemorySize, GEMM_SMEM);

    // CSR build + degree norm
    k_zero_deg<<<(NN + 255) / 256, 256>>>();
    k_deg<<<(EE + 255) / 256, 256>>>(col);
    k_scan<<<1, 1024>>>();
    k_dinv_cursor<<<(NN + 255) / 256, 256>>>();
    k_fill<<<(EE + 255) / 256, 256>>>(row, col);

    int AGG_GRID = (NN + 7) / 8;
    int GB = (NN + BM - 1) / BM;

    // conv1: h1 = relu(agg@W1r^T + b1 + x@W1x^T)
    k_agg1<<<AGG_GRID, 256>>>((const float4*)x);                      // bufA = agg
    k_gemm<<<GB, 256, GEMM_SMEM>>>(nullptr, 1, 2, W1r, b1, 0);        // bufB = agg@W1r^T + b1
    k_gemm<<<GB, 256, GEMM_SMEM>>>(x, 0, 2, W1x, nullptr, FL_ACC | FL_RELU); // bufB = h1

    // conv2: h2 = relu(dinv*(hq2 self+neigh) + b2), hq2 = (h1@W2^T)*dinv
    k_gemm<<<GB, 256, GEMM_SMEM>>>(nullptr, 2, 1, W2, nullptr, FL_DINV);  // bufA = hq2
    k_aggn<<<AGG_GRID, 256>>>(1, 2, b2, 1);                               // bufB = h2

    // conv3: h3 = dinv*(hq3 self+neigh) + b3
    k_gemm<<<GB, 256, GEMM_SMEM>>>(nullptr, 2, 1, W3, nullptr, FL_DINV);  // bufA = hq3
    k_aggn<<<AGG_GRID, 256>>>(1, 2, b3, 0);                               // bufB = h3

    // pooling + normalize + classifier
    k_zero_pool<<<(GG * HH + 255) / 256, 256>>>();
    k_pool<<<(NN * HH + 255) / 256, 256>>>(batch, 2);
    k_cnt<<<(NN + 255) / 256, 256>>>(batch);
    k_final1<<<GG, HH>>>(out);
    k_final2<<<GG, HH>>>(Wl, bl, out);
}

// round 2
// speedup vs baseline: 1.0046x; 1.0046x over previous
#include <cuda_runtime.h>
#include <math.h>

#define NN 50000
#define EE 800000
#define HH 128
#define GG 128
#define CC 10
#define BM 64

// ---------------- static device scratch (no allocations allowed) ----------------
__device__ int   g_deg[NN];
__device__ int   g_starts[NN + 1];
__device__ int   g_cursor[NN];
__device__ int   g_src[EE];
__device__ float g_dinv[NN];
__device__ float g_bufA[(size_t)NN * HH];
__device__ float g_bufB[(size_t)NN * HH];
__device__ float g_pool[GG * HH];
__device__ float g_cnt[GG];

__device__ __forceinline__ float* dev_buf(int s) { return s == 1 ? g_bufA : g_bufB; }

// ---------------- graph preprocessing ----------------
__global__ void k_zero_deg() {
    int i = blockIdx.x * blockDim.x + threadIdx.x;
    if (i < NN) g_deg[i] = 0;
}

__global__ void k_deg(const int* __restrict__ col) {
    int e = blockIdx.x * blockDim.x + threadIdx.x;
    if (e < EE) atomicAdd(&g_deg[col[e]], 1);
}

// single-block exclusive scan of g_deg -> g_starts (N=50000, 1024 threads)
__global__ void k_scan() {
    __shared__ int warp_sums[32];
    __shared__ int carry_s;
    int tid = threadIdx.x;
    int lane = tid & 31, wid = tid >> 5;
    if (tid == 0) carry_s = 0;
    __syncthreads();
    for (int base = 0; base < NN; base += 1024) {
        int i = base + tid;
        int v = (i < NN) ? g_deg[i] : 0;
        int s = v;
        #pragma unroll
        for (int o = 1; o < 32; o <<= 1) {
            int t = __shfl_up_sync(0xFFFFFFFFu, s, o);
            if (lane >= o) s += t;
        }
        if (lane == 31) warp_sums[wid] = s;
        __syncthreads();
        if (wid == 0) {
            int ws = warp_sums[lane];
            #pragma unroll
            for (int o = 1; o < 32; o <<= 1) {
                int t = __shfl_up_sync(0xFFFFFFFFu, ws, o);
                if (lane >= o) ws += t;
            }
            warp_sums[lane] = ws;
        }
        __syncthreads();
        int offset = (wid > 0) ? warp_sums[wid - 1] : 0;
        int incl = s + offset;
        int carry = carry_s;
        if (i < NN) g_starts[i] = carry + incl - v;  // exclusive
        __syncthreads();
        if (tid == 1023) carry_s = carry + incl;
        __syncthreads();
    }
    if (tid == 0) g_starts[NN] = carry_s;
}

__global__ void k_dinv_cursor() {
    int i = blockIdx.x * blockDim.x + threadIdx.x;
    if (i < NN) {
        g_dinv[i] = rsqrtf((float)(g_deg[i] + 1));  // +1 self loop
        g_cursor[i] = g_starts[i];
    }
}

__global__ void k_fill(const int* __restrict__ row, const int* __restrict__ col) {
    int e = blockIdx.x * blockDim.x + threadIdx.x;
    if (e < EE) {
        int c = col[e];
        int p = atomicAdd(&g_cursor[c], 1);
        g_src[p] = row[e];
    }
}

// ---------------- aggregation (warp per node, float4 lanes) ----------------
__global__ void k_agg1(const float4* __restrict__ x4) {
    int node = blockIdx.x * 8 + (threadIdx.x >> 5);
    if (node >= NN) return;
    int lane = threadIdx.x & 31;
    float4 acc = make_float4(0.f, 0.f, 0.f, 0.f);
    int s = g_starts[node], e = g_starts[node + 1];
    for (int j = s; j < e; j++) {
        int u = g_src[j];
        float4 v = __ldg(&x4[(size_t)u * 32 + lane]);
        acc.x += v.x; acc.y += v.y; acc.z += v.z; acc.w += v.w;
    }
    ((float4*)g_bufA)[(size_t)node * 32 + lane] = acc;
}

// out[i] = dinv[i]*(hq[i] + sum_src hq[src]) + b ; optional relu
__global__ void k_aggn(int in_sel, int out_sel, const float* __restrict__ bias, int relu) {
    int node = blockIdx.x * 8 + (threadIdx.x >> 5);
    if (node >= NN) return;
    int lane = threadIdx.x & 31;
    const float4* hq = (const float4*)dev_buf(in_sel);
    float4* outp = (float4*)dev_buf(out_sel);
    float4 acc = hq[(size_t)node * 32 + lane];  // self term
    int s = g_starts[node], e = g_starts[node + 1];
    for (int j = s; j < e; j++) {
        int u = g_src[j];
        float4 v = __ldg(&hq[(size_t)u * 32 + lane]);
        acc.x += v.x; acc.y += v.y; acc.z += v.z; acc.w += v.w;
    }
    float dv = g_dinv[node];
    float4 b = ((const float4*)bias)[lane];
    float4 r;
    r.x = fmaf(acc.x, dv, b.x);
    r.y = fmaf(acc.y, dv, b.y);
    r.z = fmaf(acc.z, dv, b.z);
    r.w = fmaf(acc.w, dv, b.w);
    if (relu) {
        r.x = fmaxf(r.x, 0.f); r.y = fmaxf(r.y, 0.f);
        r.z = fmaxf(r.z, 0.f); r.w = fmaxf(r.w, 0.f);
    }
    outp[(size_t)node * 32 + lane] = r;
}

// ---------------- GEMM: C[M,128] = A[M,128] @ W[128,128]^T  (C[m,n]=sum_k A[m,k]W[n,k]) ----------------
// flags: 1 = accumulate into existing C, 2 = relu, 4 = scale output row by g_dinv[m]
#define FL_ACC  1
#define FL_RELU 2
#define FL_DINV 4
#define GEMM_SMEM (128 * 129 * 4 + BM * 128 * 4)

__global__ void k_gemm(const float* __restrict__ A_ext, int a_sel, int c_sel,
                       const float* __restrict__ W,
                       const float* __restrict__ bias, int flags) {
    extern __shared__ float sm[];
    float* Wt = sm;               // [128][129] transposed W: Wt[k*129+n] = W[n,k]
    float* As = sm + 128 * 129;   // [BM][128]
    const float* A = a_sel ? dev_buf(a_sel) : A_ext;
    float* Cm = dev_buf(c_sel);
    int tid = threadIdx.x, lane = tid & 31, warp = tid >> 5;
    int m0 = blockIdx.x * BM;

    // load W transposed (coalesced reads, conflict-free pitch-129 writes)
    #pragma unroll
    for (int i = 0; i < 64; i++) {
        int idx = tid + i * 256;            // idx = n*128 + k
        int k = idx & 127, n = idx >> 7;
        Wt[k * 129 + n] = W[idx];
    }
    // load A tile (float4 coalesced), zero-fill tail
    const float4* A4 = (const float4*)A;
    float4* As4 = (float4*)As;
    #pragma unroll
    for (int i = 0; i < 8; i++) {
        int idx4 = tid + i * 256;           // 0..2047 (64 rows * 32 float4)
        int rrow = idx4 >> 5, cc = idx4 & 31;
        int m = m0 + rrow;
        float4 v = make_float4(0.f, 0.f, 0.f, 0.f);
        if (m < NN) v = __ldg(&A4[(size_t)m * 32 + cc]);
        As4[idx4] = v;
    }
    __syncthreads();

    float acc[8][4];
    #pragma unroll
    for (int i = 0; i < 8; i++)
        #pragma unroll
        for (int j = 0; j < 4; j++) acc[i][j] = 0.f;

    int r = warp * 8;
    #pragma unroll 4
    for (int k = 0; k < 128; k++) {
        float w0 = Wt[k * 129 + lane];
        float w1 = Wt[k * 129 + lane + 32];
        float w2 = Wt[k * 129 + lane + 64];
        float w3 = Wt[k * 129 + lane + 96];
        #pragma unroll
        for (int i = 0; i < 8; i++) {
            float a = As[(r + i) * 128 + k];
            acc[i][0] = fmaf(a, w0, acc[i][0]);
            acc[i][1] = fmaf(a, w1, acc[i][1]);
            acc[i][2] = fmaf(a, w2, acc[i][2]);
            acc[i][3] = fmaf(a, w3, acc[i][3]);
        }
    }

    #pragma unroll
    for (int i = 0; i < 8; i++) {
        int m = m0 + r + i;
        if (m >= NN) continue;
        float dv = (flags & FL_DINV) ? g_dinv[m] : 1.f;
        #pragma unroll
        for (int j = 0; j < 4; j++) {
            int c = lane + 32 * j;
            float v = acc[i][j];
            if (flags & FL_ACC) v += Cm[(size_t)m * 128 + c];
            if (bias) v += bias[c];
            if (flags & FL_DINV) v *= dv;
            if (flags & FL_RELU) v = fmaxf(v, 0.f);
            Cm[(size_t)m * 128 + c] = v;
        }
    }
}

// ---------------- pooling + normalize + classifier ----------------
__global__ void k_zero_pool() {
    int i = blockIdx.x * blockDim.x + threadIdx.x;
    if (i < GG * HH) g_pool[i] = 0.f;
    if (i < GG) g_cnt[i] = 0.f;
}

__global__ void k_pool(const int* __restrict__ batch, int h_sel) {
    const float* h = dev_buf(h_sel);
    int id = blockIdx.x * blockDim.x + threadIdx.x;
    if (id < NN * HH) {
        int node = id >> 7;
        atomicAdd(&g_pool[batch[node] * HH + (id & 127)], h[id]);
    }
}

__global__ void k_cnt(const int* __restrict__ batch) {
    int i = blockIdx.x * blockDim.x + threadIdx.x;
    if (i < NN) atomicAdd(&g_cnt[batch[i]], 1.f);
}

__global__ void k_final1(float* __restrict__ dout) {
    __shared__ float ws[4];
    int g = blockIdx.x, t = threadIdx.x;
    float c = fmaxf(g_cnt[g], 1.f);
    float v = g_pool[g * HH + t] / c;
    float s = v * v;
    #pragma unroll
    for (int o = 16; o > 0; o >>= 1) s += __shfl_down_sync(0xFFFFFFFFu, s, o);
    if ((t & 31) == 0) ws[t >> 5] = s;
    __syncthreads();
    float tot = ws[0] + ws[1] + ws[2] + ws[3];
    float nrm = fmaxf(sqrtf(tot), 1e-12f);
    dout[g * HH + t] = v / nrm;
}

__global__ void k_final2(const float* __restrict__ Wl, const float* __restrict__ bl,
                         float* __restrict__ dout) {
    __shared__ float xs[HH];
    __shared__ float winv[CC];
    int g = blockIdx.x, t = threadIdx.x;
    xs[t] = dout[g * HH + t];
    if (t < CC) {
        float s = 0.f;
        #pragma unroll 8
        for (int k = 0; k < HH; k++) { float w = Wl[t * HH + k]; s = fmaf(w, w, s); }
        winv[t] = 1.f / fmaxf(sqrtf(s), 1e-12f);
    }
    __syncthreads();
    if (t < CC) {
        float s = 0.f;
        #pragma unroll 8
        for (int k = 0; k < HH; k++) s = fmaf(xs[k], Wl[t * HH + k], s);
        dout[GG * HH + g * CC + t] = fmaf(s, winv[t], bl[t]);
    }
}

// ---------------- launch ----------------
extern "C" void kernel_launch(void* const* d_in, const int* in_sizes, int n_in,
                              void* d_out, int out_size) {
    const float* x    = (const float*)d_in[0];
    const int*   ei   = (const int*)d_in[1];
    const int*   batch= (const int*)d_in[2];
    const float* W1r  = (const float*)d_in[3];
    const float* b1   = (const float*)d_in[4];
    const float* W1x  = (const float*)d_in[5];
    const float* W2   = (const float*)d_in[6];
    const float* b2   = (const float*)d_in[7];
    const float* W3   = (const float*)d_in[8];
    const float* b3   = (const float*)d_in[9];
    const float* Wl   = (const float*)d_in[10];
    const float* bl   = (const float*)d_in[11];
    const int* row = ei;
    const int* col = ei + EE;
    float* out = (float*)d_out;

    cudaFuncSetAttribute(k_gemm, cudaFuncAttributeMaxDynamicSharedMemorySize, GEMM_SMEM);

    // CSR build + degree norm
    k_zero_deg<<<(NN + 255) / 256, 256>>>();
    k_deg<<<(EE + 255) / 256, 256>>>(col);
    k_scan<<<1, 1024>>>();
    k_dinv_cursor<<<(NN + 255) / 256, 256>>>();
    k_fill<<<(EE + 255) / 256, 256>>>(row, col);

    int AGG_GRID = (NN + 7) / 8;
    int GB = (NN + BM - 1) / BM;

    // conv1: h1 = relu(agg@W1r^T + b1 + x@W1x^T)
    k_agg1<<<AGG_GRID, 256>>>((const float4*)x);                      // bufA = agg
    k_gemm<<<GB, 256, GEMM_SMEM>>>(nullptr, 1, 2, W1r, b1, 0);        // bufB = agg@W1r^T + b1
    k_gemm<<<GB, 256, GEMM_SMEM>>>(x, 0, 2, W1x, nullptr, FL_ACC | FL_RELU); // bufB = h1

    // conv2: h2 = relu(dinv*(hq2 self+neigh) + b2), hq2 = (h1@W2^T)*dinv
    k_gemm<<<GB, 256, GEMM_SMEM>>>(nullptr, 2, 1, W2, nullptr, FL_DINV);  // bufA = hq2
    k_aggn<<<AGG_GRID, 256>>>(1, 2, b2, 1);                               // bufB = h2

    // conv3: h3 = dinv*(hq3 self+neigh) + b3
    k_gemm<<<GB, 256, GEMM_SMEM>>>(nullptr, 2, 1, W3, nullptr, FL_DINV);  // bufA = hq3
    k_aggn<<<AGG_GRID, 256>>>(1, 2, b3, 0);                               // bufB = h3

    // pooling + normalize + classifier
    k_zero_pool<<<(GG * HH + 255) / 256, 256>>>();
    k_pool<<<(NN * HH + 255) / 256, 256>>>(batch, 2);
    k_cnt<<<(NN + 255) / 256, 256>>>(batch);
    k_final1<<<GG, HH>>>(out);
    k_final2<<<GG, HH>>>(Wl, bl, out);
}

// round 4
// speedup vs baseline: 1.2086x; 1.2030x over previous
#include <cuda_runtime.h>
#include <cuda_bf16.h>
#include <math.h>
#include <cstdint>

#define NN 50000
#define EE 800000
#define HH 128
#define GG 128
#define CC 10

// ---------------- static device scratch ----------------
__device__ int   g_deg[NN];
__device__ int   g_starts[NN + 1];
__device__ int   g_cursor[NN];
__device__ int   g_src[EE];
__device__ float g_dinv[NN];
__device__ float g_bufA[(size_t)NN * HH];
__device__ float g_bufB[(size_t)NN * HH];
__device__ float g_pool[GG * HH];
__device__ float g_cnt[GG];

__device__ __forceinline__ float* dev_buf(int s) { return s == 1 ? g_bufA : g_bufB; }

// ---------------- graph preprocessing ----------------
__global__ void k_zero_deg() {
    int i = blockIdx.x * blockDim.x + threadIdx.x;
    if (i < NN) g_deg[i] = 0;
}
__global__ void k_deg(const int* __restrict__ col) {
    int e = blockIdx.x * blockDim.x + threadIdx.x;
    if (e < EE) atomicAdd(&g_deg[col[e]], 1);
}
__global__ void k_scan() {
    __shared__ int warp_sums[32];
    __shared__ int carry_s;
    int tid = threadIdx.x;
    int lane = tid & 31, wid = tid >> 5;
    if (tid == 0) carry_s = 0;
    __syncthreads();
    for (int base = 0; base < NN; base += 1024) {
        int i = base + tid;
        int v = (i < NN) ? g_deg[i] : 0;
        int s = v;
        #pragma unroll
        for (int o = 1; o < 32; o <<= 1) {
            int t = __shfl_up_sync(0xFFFFFFFFu, s, o);
            if (lane >= o) s += t;
        }
        if (lane == 31) warp_sums[wid] = s;
        __syncthreads();
        if (wid == 0) {
            int ws = warp_sums[lane];
            #pragma unroll
            for (int o = 1; o < 32; o <<= 1) {
                int t = __shfl_up_sync(0xFFFFFFFFu, ws, o);
                if (lane >= o) ws += t;
            }
            warp_sums[lane] = ws;
        }
        __syncthreads();
        int offset = (wid > 0) ? warp_sums[wid - 1] : 0;
        int incl = s + offset;
        int carry = carry_s;
        if (i < NN) g_starts[i] = carry + incl - v;
        __syncthreads();
        if (tid == 1023) carry_s = carry + incl;
        __syncthreads();
    }
    if (tid == 0) g_starts[NN] = carry_s;
}
__global__ void k_dinv_cursor() {
    int i = blockIdx.x * blockDim.x + threadIdx.x;
    if (i < NN) {
        g_dinv[i] = rsqrtf((float)(g_deg[i] + 1));
        g_cursor[i] = g_starts[i];
    }
}
__global__ void k_fill(const int* __restrict__ row, const int* __restrict__ col) {
    int e = blockIdx.x * blockDim.x + threadIdx.x;
    if (e < EE) {
        int c = col[e];
        int p = atomicAdd(&g_cursor[c], 1);
        g_src[p] = row[e];
    }
}

// ---------------- aggregation (warp per node, float4 lanes) ----------------
__global__ void k_agg1(const float4* __restrict__ x4) {
    int node = blockIdx.x * 8 + (threadIdx.x >> 5);
    if (node >= NN) return;
    int lane = threadIdx.x & 31;
    float4 acc = make_float4(0.f, 0.f, 0.f, 0.f);
    int s = g_starts[node], e = g_starts[node + 1];
    for (int j = s; j < e; j++) {
        int u = g_src[j];
        float4 v = __ldg(&x4[(size_t)u * 32 + lane]);
        acc.x += v.x; acc.y += v.y; acc.z += v.z; acc.w += v.w;
    }
    ((float4*)g_bufA)[(size_t)node * 32 + lane] = acc;
}

__global__ void k_aggn(int in_sel, int out_sel, const float* __restrict__ bias, int relu) {
    int node = blockIdx.x * 8 + (threadIdx.x >> 5);
    if (node >= NN) return;
    int lane = threadIdx.x & 31;
    const float4* hq = (const float4*)dev_buf(in_sel);
    float4* outp = (float4*)dev_buf(out_sel);
    float4 acc = hq[(size_t)node * 32 + lane];
    int s = g_starts[node], e = g_starts[node + 1];
    for (int j = s; j < e; j++) {
        int u = g_src[j];
        float4 v = __ldg(&hq[(size_t)u * 32 + lane]);
        acc.x += v.x; acc.y += v.y; acc.z += v.z; acc.w += v.w;
    }
    float dv = g_dinv[node];
    float4 b = ((const float4*)bias)[lane];
    float4 r;
    r.x = fmaf(acc.x, dv, b.x);
    r.y = fmaf(acc.y, dv, b.y);
    r.z = fmaf(acc.z, dv, b.z);
    r.w = fmaf(acc.w, dv, b.w);
    if (relu) {
        r.x = fmaxf(r.x, 0.f); r.y = fmaxf(r.y, 0.f);
        r.z = fmaxf(r.z, 0.f); r.w = fmaxf(r.w, 0.f);
    }
    outp[(size_t)node * 32 + lane] = r;
}

// ---------------- HMMA GEMM: C[M,128] = A[M,128] @ W[128,128]^T ----------------
// Split precision bf16: A = Ah+Al, W = Wh+Wl; C = Ah*Wh + Ah*Wl + Al*Wh.
// mma.sync.m16n8k16.row.col: A row-major [16,16], B col-major (= W[n][k] rows).
#define FL_ACC  1
#define FL_RELU 2
#define FL_DINV 4
#define APITCH 136   // bf16 pitch: 272B rows -> conflict-free 8-row fragment loads
#define GEMM_SMEM (4 * 128 * APITCH * 2)

__device__ __forceinline__ void mma16816(float* c, const uint32_t* a, uint32_t b0, uint32_t b1) {
    asm volatile("mma.sync.aligned.m16n8k16.row.col.f32.bf16.bf16.f32 "
        "{%0,%1,%2,%3}, {%4,%5,%6,%7}, {%8,%9}, {%0,%1,%2,%3};"
        : "+f"(c[0]), "+f"(c[1]), "+f"(c[2]), "+f"(c[3])
        : "r"(a[0]), "r"(a[1]), "r"(a[2]), "r"(a[3]), "r"(b0), "r"(b1));
}

__global__ __launch_bounds__(256, 1) void k_gemm_mma(
    const float* __restrict__ A_ext, int a_sel, int c_sel,
    const float* __restrict__ W, const float* __restrict__ bias, int flags)
{
    extern __shared__ __nv_bfloat16 sm[];
    __nv_bfloat16* Ah = sm;
    __nv_bfloat16* Al = Ah + 128 * APITCH;
    __nv_bfloat16* Wh = Al + 128 * APITCH;
    __nv_bfloat16* Wl = Wh + 128 * APITCH;
    const float* A = a_sel ? dev_buf(a_sel) : A_ext;
    float* Cm = dev_buf(c_sel);
    int tid = threadIdx.x, wid = tid >> 5, lane = tid & 31;
    int m0 = blockIdx.x * 128;

    // convert A tile -> bf16 hi/lo (padded row-major)
    #pragma unroll 4
    for (int p = tid; p < 8192; p += 256) {
        int row = p >> 6;
        int k2 = (p & 63) * 2;
        int m = m0 + row;
        float2 v = make_float2(0.f, 0.f);
        if (m < NN) v = __ldg((const float2*)&A[(size_t)m * 128 + k2]);
        __nv_bfloat16 h0 = __float2bfloat16(v.x);
        __nv_bfloat16 h1 = __float2bfloat16(v.y);
        __nv_bfloat16 l0 = __float2bfloat16(v.x - __bfloat162float(h0));
        __nv_bfloat16 l1 = __float2bfloat16(v.y - __bfloat162float(h1));
        __nv_bfloat162 hv; hv.x = h0; hv.y = h1;
        __nv_bfloat162 lv; lv.x = l0; lv.y = l1;
        *(__nv_bfloat162*)&Ah[row * APITCH + k2] = hv;
        *(__nv_bfloat162*)&Al[row * APITCH + k2] = lv;
    }
    // convert W tile -> bf16 hi/lo
    #pragma unroll 4
    for (int p = tid; p < 8192; p += 256) {
        int n = p >> 6;
        int k2 = (p & 63) * 2;
        float2 v = __ldg((const float2*)&W[(size_t)n * 128 + k2]);
        __nv_bfloat16 h0 = __float2bfloat16(v.x);
        __nv_bfloat16 h1 = __float2bfloat16(v.y);
        __nv_bfloat16 l0 = __float2bfloat16(v.x - __bfloat162float(h0));
        __nv_bfloat16 l1 = __float2bfloat16(v.y - __bfloat162float(h1));
        __nv_bfloat162 hv; hv.x = h0; hv.y = h1;
        __nv_bfloat162 lv; lv.x = l0; lv.y = l1;
        *(__nv_bfloat162*)&Wh[n * APITCH + k2] = hv;
        *(__nv_bfloat162*)&Wl[n * APITCH + k2] = lv;
    }
    __syncthreads();

    // warp tiling: warp (wid&3) -> 32 M-rows, (wid>>2) -> 64 N-cols
    int wm = (wid & 3) * 32;
    int wn = (wid >> 2) * 64;
    int g = lane >> 2, tig = lane & 3;

    float c[2][8][4];
    #pragma unroll
    for (int mt = 0; mt < 2; mt++)
        #pragma unroll
        for (int nt = 0; nt < 8; nt++)
            #pragma unroll
            for (int j = 0; j < 4; j++) c[mt][nt][j] = 0.f;

    #pragma unroll 1
    for (int pass = 0; pass < 3; pass++) {
        const __nv_bfloat16* As = (pass == 2) ? Al : Ah;
        const __nv_bfloat16* Ws = (pass == 1) ? Wl : Wh;
        #pragma unroll
        for (int ks = 0; ks < 8; ks++) {
            int kb = ks * 16 + 2 * tig;
            uint32_t a[2][4];
            #pragma unroll
            for (int mt = 0; mt < 2; mt++) {
                int r = wm + mt * 16 + g;
                a[mt][0] = *(const uint32_t*)&As[r * APITCH + kb];
                a[mt][1] = *(const uint32_t*)&As[(r + 8) * APITCH + kb];
                a[mt][2] = *(const uint32_t*)&As[r * APITCH + kb + 8];
                a[mt][3] = *(const uint32_t*)&As[(r + 8) * APITCH + kb + 8];
            }
            #pragma unroll
            for (int nt = 0; nt < 8; nt++) {
                int n = wn + nt * 8 + g;
                uint32_t b0 = *(const uint32_t*)&Ws[n * APITCH + kb];
                uint32_t b1 = *(const uint32_t*)&Ws[n * APITCH + kb + 8];
                mma16816(c[0][nt], a[0], b0, b1);
                mma16816(c[1][nt], a[1], b0, b1);
            }
        }
    }

    // epilogue: thread holds C[row][col], C[row][col+1], C[row+8][col], C[row+8][col+1]
    #pragma unroll
    for (int mt = 0; mt < 2; mt++) {
        #pragma unroll
        for (int half = 0; half < 2; half++) {
            int m = m0 + wm + mt * 16 + g + half * 8;
            if (m >= NN) continue;
            float dv = (flags & FL_DINV) ? g_dinv[m] : 1.f;
            #pragma unroll
            for (int nt = 0; nt < 8; nt++) {
                int col = wn + nt * 8 + 2 * tig;
                float vx = c[mt][nt][half * 2 + 0];
                float vy = c[mt][nt][half * 2 + 1];
                float* dst = &Cm[(size_t)m * 128 + col];
                if (flags & FL_ACC) {
                    float2 o = *(const float2*)dst;
                    vx += o.x; vy += o.y;
                }
                if (bias) {
                    float2 b2 = __ldg((const float2*)&bias[col]);
                    vx += b2.x; vy += b2.y;
                }
                if (flags & FL_DINV) { vx *= dv; vy *= dv; }
                if (flags & FL_RELU) { vx = fmaxf(vx, 0.f); vy = fmaxf(vy, 0.f); }
                float2 r2; r2.x = vx; r2.y = vy;
                *(float2*)dst = r2;
            }
        }
    }
}

// ---------------- pooling + normalize + classifier ----------------
__global__ void k_zero_pool() {
    int i = blockIdx.x * blockDim.x + threadIdx.x;
    if (i < GG * HH) g_pool[i] = 0.f;
    if (i < GG) g_cnt[i] = 0.f;
}

// batch is sorted: accumulate runs in registers, flush on graph change
__global__ void k_pool2(const int* __restrict__ batch, int h_sel) {
    const float* h = dev_buf(h_sel);
    int c = threadIdx.x;
    int n0 = blockIdx.x * 64;
    int n1 = n0 + 64; if (n1 > NN) n1 = NN;
    if (n0 >= NN) return;
    float acc = 0.f;
    int cur = __ldg(&batch[n0]);
    for (int n = n0; n < n1; n++) {
        int b = __ldg(&batch[n]);
        if (b != cur) { atomicAdd(&g_pool[cur * HH + c], acc); acc = 0.f; cur = b; }
        acc += h[(size_t)n * HH + c];
    }
    atomicAdd(&g_pool[cur * HH + c], acc);
}

__global__ void k_cnt(const int* __restrict__ batch) {
    int i = blockIdx.x * blockDim.x + threadIdx.x;
    if (i < NN) atomicAdd(&g_cnt[batch[i]], 1.f);
}

__global__ void k_final1(float* __restrict__ dout) {
    __shared__ float ws[4];
    int g = blockIdx.x, t = threadIdx.x;
    float c = fmaxf(g_cnt[g], 1.f);
    float v = g_pool[g * HH + t] / c;
    float s = v * v;
    #pragma unroll
    for (int o = 16; o > 0; o >>= 1) s += __shfl_down_sync(0xFFFFFFFFu, s, o);
    if ((t & 31) == 0) ws[t >> 5] = s;
    __syncthreads();
    float tot = ws[0] + ws[1] + ws[2] + ws[3];
    float nrm = fmaxf(sqrtf(tot), 1e-12f);
    dout[g * HH + t] = v / nrm;
}

__global__ void k_final2(const float* __restrict__ Wl, const float* __restrict__ bl,
                         float* __restrict__ dout) {
    __shared__ float xs[HH];
    __shared__ float winv[CC];
    int g = blockIdx.x, t = threadIdx.x;
    xs[t] = dout[g * HH + t];
    if (t < CC) {
        float s = 0.f;
        #pragma unroll 8
        for (int k = 0; k < HH; k++) { float w = Wl[t * HH + k]; s = fmaf(w, w, s); }
        winv[t] = 1.f / fmaxf(sqrtf(s), 1e-12f);
    }
    __syncthreads();
    if (t < CC) {
        float s = 0.f;
        #pragma unroll 8
        for (int k = 0; k < HH; k++) s = fmaf(xs[k], Wl[t * HH + k], s);
        dout[GG * HH + g * CC + t] = fmaf(s, winv[t], bl[t]);
    }
}

// ---------------- launch ----------------
extern "C" void kernel_launch(void* const* d_in, const int* in_sizes, int n_in,
                              void* d_out, int out_size) {
    const float* x    = (const float*)d_in[0];
    const int*   ei   = (const int*)d_in[1];
    const int*   batch= (const int*)d_in[2];
    const float* W1r  = (const float*)d_in[3];
    const float* b1   = (const float*)d_in[4];
    const float* W1x  = (const float*)d_in[5];
    const float* W2   = (const float*)d_in[6];
    const float* b2   = (const float*)d_in[7];
    const float* W3   = (const float*)d_in[8];
    const float* b3   = (const float*)d_in[9];
    const float* Wl   = (const float*)d_in[10];
    const float* bl   = (const float*)d_in[11];
    const int* row = ei;
    const int* col = ei + EE;
    float* out = (float*)d_out;

    cudaFuncSetAttribute(k_gemm_mma, cudaFuncAttributeMaxDynamicSharedMemorySize, GEMM_SMEM);

    // CSR build + degree norm
    k_zero_deg<<<(NN + 255) / 256, 256>>>();
    k_deg<<<(EE + 255) / 256, 256>>>(col);
    k_scan<<<1, 1024>>>();
    k_dinv_cursor<<<(NN + 255) / 256, 256>>>();
    k_fill<<<(EE + 255) / 256, 256>>>(row, col);

    int AGG_GRID = (NN + 7) / 8;
    int GB = (NN + 127) / 128;

    // conv1: h1 = relu(agg@W1r^T + b1 + x@W1x^T)
    k_agg1<<<AGG_GRID, 256>>>((const float4*)x);                                  // bufA = agg
    k_gemm_mma<<<GB, 256, GEMM_SMEM>>>(nullptr, 1, 2, W1r, b1, 0);                // bufB = agg@W1r^T + b1
    k_gemm_mma<<<GB, 256, GEMM_SMEM>>>(x, 0, 2, W1x, nullptr, FL_ACC | FL_RELU);  // bufB = h1

    // conv2: h2 = relu(dinv*(hq2 self+neigh) + b2), hq2 = (h1@W2^T)*dinv
    k_gemm_mma<<<GB, 256, GEMM_SMEM>>>(nullptr, 2, 1, W2, nullptr, FL_DINV);      // bufA = hq2
    k_aggn<<<AGG_GRID, 256>>>(1, 2, b2, 1);                                       // bufB = h2

    // conv3: h3 = dinv*(hq3 self+neigh) + b3
    k_gemm_mma<<<GB, 256, GEMM_SMEM>>>(nullptr, 2, 1, W3, nullptr, FL_DINV);      // bufA = hq3
    k_aggn<<<AGG_GRID, 256>>>(1, 2, b3, 0);                                       // bufB = h3

    // pooling + normalize + classifier
    k_zero_pool<<<(GG * HH + 255) / 256, 256>>>();
    k_pool2<<<(NN + 63) / 64, 128>>>(batch, 2);
    k_cnt<<<(NN + 255) / 256, 256>>>(batch);
    k_final1<<<GG, HH>>>(out);
    k_final2<<<GG, HH>>>(Wl, bl, out);
}

// round 5
// speedup vs baseline: 1.3445x; 1.1125x over previous
#include <cuda_runtime.h>
#include <cuda_bf16.h>
#include <math.h>
#include <cstdint>

#define NN 50000
#define EE 800000
#define HH 128
#define GG 128
#define CC 10

// ---------------- static device scratch ----------------
__device__ int   g_deg[NN];
__device__ int   g_starts[NN + 1];
__device__ int   g_cursor[NN];
__device__ int   g_src[EE];
__device__ float g_dinv[NN];
__device__ float g_bufA[(size_t)NN * HH];   // fp32 hq buffers
__device__ float g_bufB[(size_t)NN * HH];   // fp32 h3 for pooling
__device__ __nv_bfloat16 g_aH[(size_t)NN * HH];  // split-bf16 pair A (agg, then h2)
__device__ __nv_bfloat16 g_aL[(size_t)NN * HH];
__device__ __nv_bfloat16 g_bH[(size_t)NN * HH];  // split-bf16 pair B (h1)
__device__ __nv_bfloat16 g_bL[(size_t)NN * HH];
__device__ __nv_bfloat16 g_WcH[4 * HH * HH];     // pre-converted weights hi/lo
__device__ __nv_bfloat16 g_WcL[4 * HH * HH];
__device__ float g_pool[GG * HH];
__device__ float g_cnt[GG];

// ---------------- zero / preprocessing ----------------
__global__ void k_zero() {
    int i = blockIdx.x * blockDim.x + threadIdx.x;
    if (i < NN) g_deg[i] = 0;
    if (i < GG * HH) g_pool[i] = 0.f;
    if (i < GG) g_cnt[i] = 0.f;
}
__global__ void k_deg(const int* __restrict__ col) {
    int e = blockIdx.x * blockDim.x + threadIdx.x;
    if (e < EE) atomicAdd(&g_deg[col[e]], 1);
}
__global__ void k_scan() {
    __shared__ int warp_sums[32];
    __shared__ int carry_s;
    int tid = threadIdx.x;
    int lane = tid & 31, wid = tid >> 5;
    if (tid == 0) carry_s = 0;
    __syncthreads();
    for (int base = 0; base < NN; base += 1024) {
        int i = base + tid;
        int v = (i < NN) ? g_deg[i] : 0;
        int s = v;
        #pragma unroll
        for (int o = 1; o < 32; o <<= 1) {
            int t = __shfl_up_sync(0xFFFFFFFFu, s, o);
            if (lane >= o) s += t;
        }
        if (lane == 31) warp_sums[wid] = s;
        __syncthreads();
        if (wid == 0) {
            int ws = warp_sums[lane];
            #pragma unroll
            for (int o = 1; o < 32; o <<= 1) {
                int t = __shfl_up_sync(0xFFFFFFFFu, ws, o);
                if (lane >= o) ws += t;
            }
            warp_sums[lane] = ws;
        }
        __syncthreads();
        int offset = (wid > 0) ? warp_sums[wid - 1] : 0;
        int incl = s + offset;
        int carry = carry_s;
        if (i < NN) g_starts[i] = carry + incl - v;
        __syncthreads();
        if (tid == 1023) carry_s = carry + incl;
        __syncthreads();
    }
    if (tid == 0) g_starts[NN] = carry_s;
}
__global__ void k_dinv_cnt(const int* __restrict__ batch) {
    int i = blockIdx.x * blockDim.x + threadIdx.x;
    if (i < NN) {
        g_dinv[i] = rsqrtf((float)(g_deg[i] + 1));
        g_cursor[i] = g_starts[i];
        atomicAdd(&g_cnt[batch[i]], 1.f);
    }
}
__global__ void k_fill(const int* __restrict__ row, const int* __restrict__ col) {
    int e = blockIdx.x * blockDim.x + threadIdx.x;
    if (e < EE) {
        int c = col[e];
        int p = atomicAdd(&g_cursor[c], 1);
        g_src[p] = row[e];
    }
}

// ---------------- weight pre-conversion ----------------
__global__ void k_convW(const float* __restrict__ W0, const float* __restrict__ W1,
                        const float* __restrict__ W2, const float* __restrict__ W3) {
    int p = blockIdx.x * blockDim.x + threadIdx.x;  // 0..16383
    if (p >= HH * HH) return;
    const float* Ws[4] = {W0, W1, W2, W3};
    #pragma unroll
    for (int w = 0; w < 4; w++) {
        float v = __ldg(&Ws[w][p]);
        __nv_bfloat16 h = __float2bfloat16(v);
        __nv_bfloat16 l = __float2bfloat16(v - __bfloat162float(h));
        g_WcH[w * HH * HH + p] = h;
        g_WcL[w * HH * HH + p] = l;
    }
}

// ---------------- aggregation ----------------
__device__ __forceinline__ void store_split4(__nv_bfloat16* H, __nv_bfloat16* L,
                                             size_t idx, float4 v) {
    __nv_bfloat16 h0 = __float2bfloat16(v.x), h1 = __float2bfloat16(v.y);
    __nv_bfloat16 h2 = __float2bfloat16(v.z), h3 = __float2bfloat16(v.w);
    __nv_bfloat162 ha; ha.x = h0; ha.y = h1;
    __nv_bfloat162 hb; hb.x = h2; hb.y = h3;
    __nv_bfloat162 la; la.x = __float2bfloat16(v.x - __bfloat162float(h0));
    la.y = __float2bfloat16(v.y - __bfloat162float(h1));
    __nv_bfloat162 lb; lb.x = __float2bfloat16(v.z - __bfloat162float(h2));
    lb.y = __float2bfloat16(v.w - __bfloat162float(h3));
    *(__nv_bfloat162*)&H[idx] = ha;
    *(__nv_bfloat162*)&H[idx + 2] = hb;
    *(__nv_bfloat162*)&L[idx] = la;
    *(__nv_bfloat162*)&L[idx + 2] = lb;
}

// gather x (fp32) -> g_aH/g_aL split bf16
__global__ void k_agg1(const float4* __restrict__ x4) {
    int node = blockIdx.x * 8 + (threadIdx.x >> 5);
    if (node >= NN) return;
    int lane = threadIdx.x & 31;
    float4 acc = make_float4(0.f, 0.f, 0.f, 0.f);
    int s = g_starts[node], e = g_starts[node + 1];
    #pragma unroll 4
    for (int j = s; j < e; j++) {
        int u = __ldg(&g_src[j]);
        float4 v = __ldg(&x4[(size_t)u * 32 + lane]);
        acc.x += v.x; acc.y += v.y; acc.z += v.z; acc.w += v.w;
    }
    store_split4(g_aH, g_aL, (size_t)node * HH + lane * 4, acc);
}

// gather g_bufA (fp32 hq), self+neigh, *dinv, +bias, optional relu;
// out_bf: write split-bf16 to g_aH/g_aL; else fp32 to g_bufB
__global__ void k_aggn(const float* __restrict__ bias, int relu, int out_bf) {
    int node = blockIdx.x * 8 + (threadIdx.x >> 5);
    if (node >= NN) return;
    int lane = threadIdx.x & 31;
    const float4* hq = (const float4*)g_bufA;
    float4 acc = hq[(size_t)node * 32 + lane];
    int s = g_starts[node], e = g_starts[node + 1];
    #pragma unroll 4
    for (int j = s; j < e; j++) {
        int u = __ldg(&g_src[j]);
        float4 v = __ldg(&hq[(size_t)u * 32 + lane]);
        acc.x += v.x; acc.y += v.y; acc.z += v.z; acc.w += v.w;
    }
    float dv = g_dinv[node];
    float4 b = ((const float4*)bias)[lane];
    float4 r;
    r.x = fmaf(acc.x, dv, b.x);
    r.y = fmaf(acc.y, dv, b.y);
    r.z = fmaf(acc.z, dv, b.z);
    r.w = fmaf(acc.w, dv, b.w);
    if (relu) {
        r.x = fmaxf(r.x, 0.f); r.y = fmaxf(r.y, 0.f);
        r.z = fmaxf(r.z, 0.f); r.w = fmaxf(r.w, 0.f);
    }
    if (out_bf) {
        store_split4(g_aH, g_aL, (size_t)node * HH + lane * 4, r);
    } else {
        ((float4*)g_bufB)[(size_t)node * 32 + lane] = r;
    }
}

// ---------------- HMMA GEMM ----------------
#define FL_RELU 2
#define FL_DINV 4
#define FL_OUTBF 8
#define APITCH 136
#define GEMM_SMEM (4 * 128 * APITCH * 2)

__device__ __forceinline__ void mma16816(float* c, const uint32_t* a, uint32_t b0, uint32_t b1) {
    asm volatile("mma.sync.aligned.m16n8k16.row.col.f32.bf16.bf16.f32 "
        "{%0,%1,%2,%3}, {%4,%5,%6,%7}, {%8,%9}, {%0,%1,%2,%3};"
        : "+f"(c[0]), "+f"(c[1]), "+f"(c[2]), "+f"(c[3])
        : "r"(a[0]), "r"(a[1]), "r"(a[2]), "r"(a[3]), "r"(b0), "r"(b1));
}

// load preconverted bf16 A tile into padded smem
__device__ __forceinline__ void load_A_pre(__nv_bfloat16* Ah, __nv_bfloat16* Al,
                                           const __nv_bfloat16* AH, const __nv_bfloat16* AL,
                                           int m0, int tid) {
    #pragma unroll 4
    for (int p = tid; p < 4096; p += 256) {
        int row = p >> 5;
        int k2 = (p & 31) * 4;
        int m = m0 + row;
        uint2 hv = make_uint2(0u, 0u), lv = make_uint2(0u, 0u);
        if (m < NN) {
            hv = __ldg((const uint2*)&AH[(size_t)m * HH + k2]);
            lv = __ldg((const uint2*)&AL[(size_t)m * HH + k2]);
        }
        *(uint2*)&Ah[row * APITCH + k2] = hv;
        *(uint2*)&Al[row * APITCH + k2] = lv;
    }
}

// load preconverted bf16 W tile into padded smem
__device__ __forceinline__ void load_W_pre(__nv_bfloat16* Wh, __nv_bfloat16* Wl,
                                           int widx, int tid) {
    const __nv_bfloat16* WH = g_WcH + (size_t)widx * HH * HH;
    const __nv_bfloat16* WL = g_WcL + (size_t)widx * HH * HH;
    #pragma unroll 4
    for (int p = tid; p < 4096; p += 256) {
        int n = p >> 5;
        int k2 = (p & 31) * 4;
        *(uint2*)&Wh[n * APITCH + k2] = __ldg((const uint2*)&WH[n * HH + k2]);
        *(uint2*)&Wl[n * APITCH + k2] = __ldg((const uint2*)&WL[n * HH + k2]);
    }
}

// convert fp32 A tile into padded smem split bf16
__device__ __forceinline__ void load_A_conv(__nv_bfloat16* Ah, __nv_bfloat16* Al,
                                            const float* A, int m0, int tid) {
    #pragma unroll 4
    for (int p = tid; p < 8192; p += 256) {
        int row = p >> 6;
        int k2 = (p & 63) * 2;
        int m = m0 + row;
        float2 v = make_float2(0.f, 0.f);
        if (m < NN) v = __ldg((const float2*)&A[(size_t)m * HH + k2]);
        __nv_bfloat16 h0 = __float2bfloat16(v.x);
        __nv_bfloat16 h1 = __float2bfloat16(v.y);
        __nv_bfloat162 hv; hv.x = h0; hv.y = h1;
        __nv_bfloat162 lv;
        lv.x = __float2bfloat16(v.x - __bfloat162float(h0));
        lv.y = __float2bfloat16(v.y - __bfloat162float(h1));
        *(__nv_bfloat162*)&Ah[row * APITCH + k2] = hv;
        *(__nv_bfloat162*)&Al[row * APITCH + k2] = lv;
    }
}

struct Frag { float c[2][8][4]; };

__device__ __forceinline__ void mma_stage(Frag& f, const __nv_bfloat16* Ah,
                                          const __nv_bfloat16* Al,
                                          const __nv_bfloat16* Wh,
                                          const __nv_bfloat16* Wl,
                                          int wm, int wn, int lane) {
    int g = lane >> 2, tig = lane & 3;
    #pragma unroll 1
    for (int pass = 0; pass < 3; pass++) {
        const __nv_bfloat16* As = (pass == 2) ? Al : Ah;
        const __nv_bfloat16* Ws = (pass == 1) ? Wl : Wh;
        #pragma unroll
        for (int ks = 0; ks < 8; ks++) {
            int kb = ks * 16 + 2 * tig;
            uint32_t a[2][4];
            #pragma unroll
            for (int mt = 0; mt < 2; mt++) {
                int r = wm + mt * 16 + g;
                a[mt][0] = *(const uint32_t*)&As[r * APITCH + kb];
                a[mt][1] = *(const uint32_t*)&As[(r + 8) * APITCH + kb];
                a[mt][2] = *(const uint32_t*)&As[r * APITCH + kb + 8];
                a[mt][3] = *(const uint32_t*)&As[(r + 8) * APITCH + kb + 8];
            }
            #pragma unroll
            for (int nt = 0; nt < 8; nt++) {
                int n = wn + nt * 8 + g;
                uint32_t b0 = *(const uint32_t*)&Ws[n * APITCH + kb];
                uint32_t b1 = *(const uint32_t*)&Ws[n * APITCH + kb + 8];
                mma16816(f.c[0][nt], a[0], b0, b1);
                mma16816(f.c[1][nt], a[1], b0, b1);
            }
        }
    }
}

// generic GEMM: C = A @ W[w0]^T (+ x @ W[w1]^T if x2) (+bias) (*dinv) (relu)
// output: fp32 to outF, or split-bf16 to outH/outL
__global__ __launch_bounds__(256, 1) void k_gemm(
    const __nv_bfloat16* __restrict__ AH, const __nv_bfloat16* __restrict__ AL,
    int w0, const float* __restrict__ x2, int w1,
    const float* __restrict__ bias, int flags,
    float* __restrict__ outF, __nv_bfloat16* __restrict__ outH, __nv_bfloat16* __restrict__ outL)
{
    extern __shared__ __nv_bfloat16 sm[];
    __nv_bfloat16* Ah = sm;
    __nv_bfloat16* Al = Ah + 128 * APITCH;
    __nv_bfloat16* Wh = Al + 128 * APITCH;
    __nv_bfloat16* Wl = Wh + 128 * APITCH;
    int tid = threadIdx.x, wid = tid >> 5, lane = tid & 31;
    int m0 = blockIdx.x * 128;
    int wm = (wid & 3) * 32;
    int wn = (wid >> 2) * 64;
    int g = lane >> 2, tig = lane & 3;

    Frag f;
    #pragma unroll
    for (int mt = 0; mt < 2; mt++)
        #pragma unroll
        for (int nt = 0; nt < 8; nt++)
            #pragma unroll
            for (int j = 0; j < 4; j++) f.c[mt][nt][j] = 0.f;

    // stage 1
    load_A_pre(Ah, Al, AH, AL, m0, tid);
    load_W_pre(Wh, Wl, w0, tid);
    __syncthreads();
    mma_stage(f, Ah, Al, Wh, Wl, wm, wn, lane);

    // optional stage 2 (fused conv1: x @ W[w1]^T)
    if (x2) {
        __syncthreads();
        load_A_conv(Ah, Al, x2, m0, tid);
        load_W_pre(Wh, Wl, w1, tid);
        __syncthreads();
        mma_stage(f, Ah, Al, Wh, Wl, wm, wn, lane);
    }

    // epilogue
    #pragma unroll
    for (int mt = 0; mt < 2; mt++) {
        #pragma unroll
        for (int half = 0; half < 2; half++) {
            int m = m0 + wm + mt * 16 + g + half * 8;
            if (m >= NN) continue;
            float dv = (flags & FL_DINV) ? g_dinv[m] : 1.f;
            #pragma unroll
            for (int nt = 0; nt < 8; nt++) {
                int col = wn + nt * 8 + 2 * tig;
                float vx = f.c[mt][nt][half * 2 + 0];
                float vy = f.c[mt][nt][half * 2 + 1];
                if (bias) {
                    float2 b2 = __ldg((const float2*)&bias[col]);
                    vx += b2.x; vy += b2.y;
                }
                if (flags & FL_DINV) { vx *= dv; vy *= dv; }
                if (flags & FL_RELU) { vx = fmaxf(vx, 0.f); vy = fmaxf(vy, 0.f); }
                if (flags & FL_OUTBF) {
                    __nv_bfloat16 h0 = __float2bfloat16(vx);
                    __nv_bfloat16 h1 = __float2bfloat16(vy);
                    __nv_bfloat162 hv; hv.x = h0; hv.y = h1;
                    __nv_bfloat162 lv;
                    lv.x = __float2bfloat16(vx - __bfloat162float(h0));
                    lv.y = __float2bfloat16(vy - __bfloat162float(h1));
                    *(__nv_bfloat162*)&outH[(size_t)m * HH + col] = hv;
                    *(__nv_bfloat162*)&outL[(size_t)m * HH + col] = lv;
                } else {
                    float2 r2; r2.x = vx; r2.y = vy;
                    *(float2*)&outF[(size_t)m * HH + col] = r2;
                }
            }
        }
    }
}

// ---------------- pooling + fused finalize ----------------
__global__ void k_pool2(const int* __restrict__ batch) {
    const float* h = g_bufB;
    int c = threadIdx.x;
    int n0 = blockIdx.x * 64;
    int n1 = n0 + 64; if (n1 > NN) n1 = NN;
    if (n0 >= NN) return;
    float acc = 0.f;
    int cur = __ldg(&batch[n0]);
    for (int n = n0; n < n1; n++) {
        int b = __ldg(&batch[n]);
        if (b != cur) { atomicAdd(&g_pool[cur * HH + c], acc); acc = 0.f; cur = b; }
        acc += h[(size_t)n * HH + c];
    }
    atomicAdd(&g_pool[cur * HH + c], acc);
}

__global__ void k_final(const float* __restrict__ Wl, const float* __restrict__ bl,
                        float* __restrict__ dout) {
    __shared__ float ws[4];
    __shared__ float xs[HH];
    __shared__ float winv[CC];
    int g = blockIdx.x, t = threadIdx.x;
    float c = fmaxf(g_cnt[g], 1.f);
    float v = g_pool[g * HH + t] / c;
    float s = v * v;
    #pragma unroll
    for (int o = 16; o > 0; o >>= 1) s += __shfl_down_sync(0xFFFFFFFFu, s, o);
    if ((t & 31) == 0) ws[t >> 5] = s;
    if (t < CC) {
        float sw = 0.f;
        #pragma unroll 8
        for (int k = 0; k < HH; k++) { float w = __ldg(&Wl[t * HH + k]); sw = fmaf(w, w, sw); }
        winv[t] = 1.f / fmaxf(sqrtf(sw), 1e-12f);
    }
    __syncthreads();
    float tot = ws[0] + ws[1] + ws[2] + ws[3];
    float nrm = fmaxf(sqrtf(tot), 1e-12f);
    float xn = v / nrm;
    dout[g * HH + t] = xn;
    xs[t] = xn;
    __syncthreads();
    if (t < CC) {
        float s2 = 0.f;
        #pragma unroll 8
        for (int k = 0; k < HH; k++) s2 = fmaf(xs[k], __ldg(&Wl[t * HH + k]), s2);
        dout[GG * HH + g * CC + t] = fmaf(s2, winv[t], bl[t]);
    }
}

// ---------------- launch ----------------
extern "C" void kernel_launch(void* const* d_in, const int* in_sizes, int n_in,
                              void* d_out, int out_size) {
    const float* x    = (const float*)d_in[0];
    const int*   ei   = (const int*)d_in[1];
    const int*   batch= (const int*)d_in[2];
    const float* W1r  = (const float*)d_in[3];
    const float* b1   = (const float*)d_in[4];
    const float* W1x  = (const float*)d_in[5];
    const float* W2   = (const float*)d_in[6];
    const float* b2   = (const float*)d_in[7];
    const float* W3   = (const float*)d_in[8];
    const float* b3   = (const float*)d_in[9];
    const float* Wl   = (const float*)d_in[10];
    const float* bl   = (const float*)d_in[11];
    const int* row = ei;
    const int* col = ei + EE;
    float* out = (float*)d_out;

    cudaFuncSetAttribute(k_gemm, cudaFuncAttributeMaxDynamicSharedMemorySize, GEMM_SMEM);

    // resolve device symbol addresses for kernel args
    __nv_bfloat16 *aH, *aL, *bH, *bL;
    cudaGetSymbolAddress((void**)&aH, g_aH);
    cudaGetSymbolAddress((void**)&aL, g_aL);
    cudaGetSymbolAddress((void**)&bH, g_bH);
    cudaGetSymbolAddress((void**)&bL, g_bL);
    float *bufA;
    cudaGetSymbolAddress((void**)&bufA, g_bufA);

    // CSR build + degree norm (+ graph counts) + weight conversion
    k_zero<<<(NN + 255) / 256, 256>>>();
    k_deg<<<(EE + 255) / 256, 256>>>(col);
    k_convW<<<(HH * HH + 255) / 256, 256>>>(W1r, W1x, W2, W3);
    k_scan<<<1, 1024>>>();
    k_dinv_cnt<<<(NN + 255) / 256, 256>>>(batch);
    k_fill<<<(EE + 255) / 256, 256>>>(row, col);

    int AGG_GRID = (NN + 7) / 8;
    int GB = (NN + 127) / 128;

    // conv1 (fused): h1 = relu(agg@W1r^T + x@W1x^T + b1) -> split bf16 (bH/bL)
    k_agg1<<<AGG_GRID, 256>>>((const float4*)x);
    k_gemm<<<GB, 256, GEMM_SMEM>>>(aH, aL, 0, x, 1, b1, FL_RELU | FL_OUTBF,
                                   nullptr, bH, bL);

    // conv2: hq2 = (h1@W2^T)*dinv -> fp32 bufA; h2 = relu(dinv*(sum)+b2) -> aH/aL
    k_gemm<<<GB, 256, GEMM_SMEM>>>(bH, bL, 2, nullptr, 0, nullptr, FL_DINV,
                                   bufA, nullptr, nullptr);
    k_aggn<<<AGG_GRID, 256>>>(b2, 1, 1);

    // conv3: hq3 = (h2@W3^T)*dinv -> bufA; h3 = dinv*(sum)+b3 -> fp32 bufB
    k_gemm<<<GB, 256, GEMM_SMEM>>>(aH, aL, 3, nullptr, 0, nullptr, FL_DINV,
                                   bufA, nullptr, nullptr);
    k_aggn<<<AGG_GRID, 256>>>(b3, 0, 0);

    // pooling + normalize + classifier
    k_pool2<<<(NN + 63) / 64, 128>>>(batch);
    k_final<<<GG, HH>>>(Wl, bl, out);
}

// round 6
// speedup vs baseline: 1.4732x; 1.0957x over previous
#include <cuda_runtime.h>
#include <cuda_bf16.h>
#include <math.h>
#include <cstdint>

#define NN 50000
#define EE 800000
#define HH 128
#define GG 128
#define CC 10
#define SCAN_BLK 49   // ceil(50000/1024)

// ---------------- static device scratch ----------------
__device__ int   g_deg[NN];
__device__ int   g_starts[NN + 1];
__device__ int   g_part[SCAN_BLK];
__device__ int   g_cursor[NN];
__device__ int   g_src[EE];
__device__ float g_dinv[NN];
__device__ float g_bufA[(size_t)NN * HH];   // fp32 hq buffers
__device__ float g_bufB[(size_t)NN * HH];   // fp32 h3 for pooling
__device__ __nv_bfloat16 g_aH[(size_t)NN * HH];  // split-bf16 pair A (agg, then h2)
__device__ __nv_bfloat16 g_aL[(size_t)NN * HH];
__device__ __nv_bfloat16 g_bH[(size_t)NN * HH];  // split-bf16 pair B (h1)
__device__ __nv_bfloat16 g_bL[(size_t)NN * HH];
__device__ __nv_bfloat16 g_WcH[4 * HH * HH];     // pre-converted weights hi/lo
__device__ __nv_bfloat16 g_WcL[4 * HH * HH];
__device__ float g_pool[GG * HH];
__device__ float g_cnt[GG];

// ---------------- zero / preprocessing ----------------
__global__ void k_zero() {
    int i = blockIdx.x * blockDim.x + threadIdx.x;
    if (i < NN) g_deg[i] = 0;
    if (i < GG * HH) g_pool[i] = 0.f;
    if (i < GG) g_cnt[i] = 0.f;
}
__global__ void k_deg(const int* __restrict__ col) {
    int e = blockIdx.x * blockDim.x + threadIdx.x;
    if (e < EE) atomicAdd(&g_deg[col[e]], 1);
}

// ---- multi-block exclusive scan of g_deg -> g_starts ----
// phase 1: per-block exclusive scan + block totals
__global__ void k_part() {
    __shared__ int warp_sums[32];
    int tid = threadIdx.x;
    int lane = tid & 31, wid = tid >> 5;
    int i = blockIdx.x * 1024 + tid;
    int v = (i < NN) ? g_deg[i] : 0;
    int s = v;
    #pragma unroll
    for (int o = 1; o < 32; o <<= 1) {
        int t = __shfl_up_sync(0xFFFFFFFFu, s, o);
        if (lane >= o) s += t;
    }
    if (lane == 31) warp_sums[wid] = s;
    __syncthreads();
    if (wid == 0) {
        int ws = warp_sums[lane];
        #pragma unroll
        for (int o = 1; o < 32; o <<= 1) {
            int t = __shfl_up_sync(0xFFFFFFFFu, ws, o);
            if (lane >= o) ws += t;
        }
        warp_sums[lane] = ws;
    }
    __syncthreads();
    int offset = (wid > 0) ? warp_sums[wid - 1] : 0;
    if (i < NN) g_starts[i] = offset + s - v;  // in-block exclusive
    if (tid == 1023) g_part[blockIdx.x] = offset + s;  // block total
}
// phase 2: scan the 49 block totals (single small block)
__global__ void k_scanpart() {
    __shared__ int buf[64];
    int t = threadIdx.x;
    buf[t] = (t < SCAN_BLK) ? g_part[t] : 0;
    __syncthreads();
    // Hillis-Steele inclusive scan over 64 entries
    #pragma unroll
    for (int o = 1; o < 64; o <<= 1) {
        int v = (t >= o) ? buf[t - o] : 0;
        __syncthreads();
        buf[t] += v;
        __syncthreads();
    }
    if (t < SCAN_BLK) g_part[t] = (t > 0) ? buf[t - 1] : 0;  // exclusive offsets
    if (t == 0) g_starts[NN] = buf[SCAN_BLK - 1];
}
// phase 3: add block offsets
__global__ void k_addoff() {
    int i = blockIdx.x * 1024 + threadIdx.x;
    if (i < NN) g_starts[i] += g_part[blockIdx.x];
}

__global__ void k_dinv_cnt(const int* __restrict__ batch) {
    int i = blockIdx.x * blockDim.x + threadIdx.x;
    if (i < NN) {
        g_dinv[i] = rsqrtf((float)(g_deg[i] + 1));
        g_cursor[i] = g_starts[i];
        atomicAdd(&g_cnt[batch[i]], 1.f);
    }
}
__global__ void k_fill(const int* __restrict__ row, const int* __restrict__ col) {
    int e = blockIdx.x * blockDim.x + threadIdx.x;
    if (e < EE) {
        int c = col[e];
        int p = atomicAdd(&g_cursor[c], 1);
        g_src[p] = row[e];
    }
}

// ---------------- weight pre-conversion ----------------
__global__ void k_convW(const float* __restrict__ W0, const float* __restrict__ W1,
                        const float* __restrict__ W2, const float* __restrict__ W3) {
    int p = blockIdx.x * blockDim.x + threadIdx.x;  // 0..16383
    if (p >= HH * HH) return;
    const float* Ws[4] = {W0, W1, W2, W3};
    #pragma unroll
    for (int w = 0; w < 4; w++) {
        float v = __ldg(&Ws[w][p]);
        __nv_bfloat16 h = __float2bfloat16(v);
        __nv_bfloat16 l = __float2bfloat16(v - __bfloat162float(h));
        g_WcH[w * HH * HH + p] = h;
        g_WcL[w * HH * HH + p] = l;
    }
}

// ---------------- aggregation ----------------
__device__ __forceinline__ void store_split4(__nv_bfloat16* H, __nv_bfloat16* L,
                                             size_t idx, float4 v) {
    __nv_bfloat16 h0 = __float2bfloat16(v.x), h1 = __float2bfloat16(v.y);
    __nv_bfloat16 h2 = __float2bfloat16(v.z), h3 = __float2bfloat16(v.w);
    __nv_bfloat162 ha; ha.x = h0; ha.y = h1;
    __nv_bfloat162 hb; hb.x = h2; hb.y = h3;
    __nv_bfloat162 la; la.x = __float2bfloat16(v.x - __bfloat162float(h0));
    la.y = __float2bfloat16(v.y - __bfloat162float(h1));
    __nv_bfloat162 lb; lb.x = __float2bfloat16(v.z - __bfloat162float(h2));
    lb.y = __float2bfloat16(v.w - __bfloat162float(h3));
    *(__nv_bfloat162*)&H[idx] = ha;
    *(__nv_bfloat162*)&H[idx + 2] = hb;
    *(__nv_bfloat162*)&L[idx] = la;
    *(__nv_bfloat162*)&L[idx + 2] = lb;
}

// gather x (fp32) -> g_aH/g_aL split bf16
__global__ void k_agg1(const float4* __restrict__ x4) {
    int node = blockIdx.x * 8 + (threadIdx.x >> 5);
    if (node >= NN) return;
    int lane = threadIdx.x & 31;
    float4 acc = make_float4(0.f, 0.f, 0.f, 0.f);
    int s = g_starts[node], e = g_starts[node + 1];
    #pragma unroll 4
    for (int j = s; j < e; j++) {
        int u = __ldg(&g_src[j]);
        float4 v = __ldg(&x4[(size_t)u * 32 + lane]);
        acc.x += v.x; acc.y += v.y; acc.z += v.z; acc.w += v.w;
    }
    store_split4(g_aH, g_aL, (size_t)node * HH + lane * 4, acc);
}

// gather g_bufA (fp32 hq), self+neigh, *dinv, +bias, optional relu;
// out_bf: write split-bf16 to g_aH/g_aL; else fp32 to g_bufB
__global__ void k_aggn(const float* __restrict__ bias, int relu, int out_bf) {
    int node = blockIdx.x * 8 + (threadIdx.x >> 5);
    if (node >= NN) return;
    int lane = threadIdx.x & 31;
    const float4* hq = (const float4*)g_bufA;
    float4 acc = hq[(size_t)node * 32 + lane];
    int s = g_starts[node], e = g_starts[node + 1];
    #pragma unroll 4
    for (int j = s; j < e; j++) {
        int u = __ldg(&g_src[j]);
        float4 v = __ldg(&hq[(size_t)u * 32 + lane]);
        acc.x += v.x; acc.y += v.y; acc.z += v.z; acc.w += v.w;
    }
    float dv = g_dinv[node];
    float4 b = ((const float4*)bias)[lane];
    float4 r;
    r.x = fmaf(acc.x, dv, b.x);
    r.y = fmaf(acc.y, dv, b.y);
    r.z = fmaf(acc.z, dv, b.z);
    r.w = fmaf(acc.w, dv, b.w);
    if (relu) {
        r.x = fmaxf(r.x, 0.f); r.y = fmaxf(r.y, 0.f);
        r.z = fmaxf(r.z, 0.f); r.w = fmaxf(r.w, 0.f);
    }
    if (out_bf) {
        store_split4(g_aH, g_aL, (size_t)node * HH + lane * 4, r);
    } else {
        ((float4*)g_bufB)[(size_t)node * 32 + lane] = r;
    }
}

// ---------------- HMMA GEMM ----------------
#define FL_RELU 2
#define FL_DINV 4
#define FL_OUTBF 8
#define APITCH 136
#define GEMM_SMEM (4 * 128 * APITCH * 2)

__device__ __forceinline__ void mma16816(float* c, const uint32_t* a, uint32_t b0, uint32_t b1) {
    asm volatile("mma.sync.aligned.m16n8k16.row.col.f32.bf16.bf16.f32 "
        "{%0,%1,%2,%3}, {%4,%5,%6,%7}, {%8,%9}, {%0,%1,%2,%3};"
        : "+f"(c[0]), "+f"(c[1]), "+f"(c[2]), "+f"(c[3])
        : "r"(a[0]), "r"(a[1]), "r"(a[2]), "r"(a[3]), "r"(b0), "r"(b1));
}

__device__ __forceinline__ void load_A_pre(__nv_bfloat16* Ah, __nv_bfloat16* Al,
                                           const __nv_bfloat16* AH, const __nv_bfloat16* AL,
                                           int m0, int tid) {
    #pragma unroll 4
    for (int p = tid; p < 4096; p += 256) {
        int row = p >> 5;
        int k2 = (p & 31) * 4;
        int m = m0 + row;
        uint2 hv = make_uint2(0u, 0u), lv = make_uint2(0u, 0u);
        if (m < NN) {
            hv = __ldg((const uint2*)&AH[(size_t)m * HH + k2]);
            lv = __ldg((const uint2*)&AL[(size_t)m * HH + k2]);
        }
        *(uint2*)&Ah[row * APITCH + k2] = hv;
        *(uint2*)&Al[row * APITCH + k2] = lv;
    }
}

__device__ __forceinline__ void load_W_pre(__nv_bfloat16* Wh, __nv_bfloat16* Wl,
                                           int widx, int tid) {
    const __nv_bfloat16* WH = g_WcH + (size_t)widx * HH * HH;
    const __nv_bfloat16* WL = g_WcL + (size_t)widx * HH * HH;
    #pragma unroll 4
    for (int p = tid; p < 4096; p += 256) {
        int n = p >> 5;
        int k2 = (p & 31) * 4;
        *(uint2*)&Wh[n * APITCH + k2] = __ldg((const uint2*)&WH[n * HH + k2]);
        *(uint2*)&Wl[n * APITCH + k2] = __ldg((const uint2*)&WL[n * HH + k2]);
    }
}

__device__ __forceinline__ void load_A_conv(__nv_bfloat16* Ah, __nv_bfloat16* Al,
                                            const float* A, int m0, int tid) {
    #pragma unroll 4
    for (int p = tid; p < 8192; p += 256) {
        int row = p >> 6;
        int k2 = (p & 63) * 2;
        int m = m0 + row;
        float2 v = make_float2(0.f, 0.f);
        if (m < NN) v = __ldg((const float2*)&A[(size_t)m * HH + k2]);
        __nv_bfloat16 h0 = __float2bfloat16(v.x);
        __nv_bfloat16 h1 = __float2bfloat16(v.y);
        __nv_bfloat162 hv; hv.x = h0; hv.y = h1;
        __nv_bfloat162 lv;
        lv.x = __float2bfloat16(v.x - __bfloat162float(h0));
        lv.y = __float2bfloat16(v.y - __bfloat162float(h1));
        *(__nv_bfloat162*)&Ah[row * APITCH + k2] = hv;
        *(__nv_bfloat162*)&Al[row * APITCH + k2] = lv;
    }
}

struct Frag { float c[2][8][4]; };

__device__ __forceinline__ void mma_stage(Frag& f, const __nv_bfloat16* Ah,
                                          const __nv_bfloat16* Al,
                                          const __nv_bfloat16* Wh,
                                          const __nv_bfloat16* Wl,
                                          int wm, int wn, int lane) {
    int g = lane >> 2, tig = lane & 3;
    #pragma unroll 1
    for (int pass = 0; pass < 3; pass++) {
        const __nv_bfloat16* As = (pass == 2) ? Al : Ah;
        const __nv_bfloat16* Ws = (pass == 1) ? Wl : Wh;
        #pragma unroll
        for (int ks = 0; ks < 8; ks++) {
            int kb = ks * 16 + 2 * tig;
            uint32_t a[2][4];
            #pragma unroll
            for (int mt = 0; mt < 2; mt++) {
                int r = wm + mt * 16 + g;
                a[mt][0] = *(const uint32_t*)&As[r * APITCH + kb];
                a[mt][1] = *(const uint32_t*)&As[(r + 8) * APITCH + kb];
                a[mt][2] = *(const uint32_t*)&As[r * APITCH + kb + 8];
                a[mt][3] = *(const uint32_t*)&As[(r + 8) * APITCH + kb + 8];
            }
            #pragma unroll
            for (int nt = 0; nt < 8; nt++) {
                int n = wn + nt * 8 + g;
                uint32_t b0 = *(const uint32_t*)&Ws[n * APITCH + kb];
                uint32_t b1 = *(const uint32_t*)&Ws[n * APITCH + kb + 8];
                mma16816(f.c[0][nt], a[0], b0, b1);
                mma16816(f.c[1][nt], a[1], b0, b1);
            }
        }
    }
}

__global__ __launch_bounds__(256, 1) void k_gemm(
    const __nv_bfloat16* __restrict__ AH, const __nv_bfloat16* __restrict__ AL,
    int w0, const float* __restrict__ x2, int w1,
    const float* __restrict__ bias, int flags,
    float* __restrict__ outF, __nv_bfloat16* __restrict__ outH, __nv_bfloat16* __restrict__ outL)
{
    extern __shared__ __nv_bfloat16 sm[];
    __nv_bfloat16* Ah = sm;
    __nv_bfloat16* Al = Ah + 128 * APITCH;
    __nv_bfloat16* Wh = Al + 128 * APITCH;
    __nv_bfloat16* Wl = Wh + 128 * APITCH;
    int tid = threadIdx.x, wid = tid >> 5, lane = tid & 31;
    int m0 = blockIdx.x * 128;
    int wm = (wid & 3) * 32;
    int wn = (wid >> 2) * 64;
    int g = lane >> 2, tig = lane & 3;

    Frag f;
    #pragma unroll
    for (int mt = 0; mt < 2; mt++)
        #pragma unroll
        for (int nt = 0; nt < 8; nt++)
            #pragma unroll
            for (int j = 0; j < 4; j++) f.c[mt][nt][j] = 0.f;

    load_A_pre(Ah, Al, AH, AL, m0, tid);
    load_W_pre(Wh, Wl, w0, tid);
    __syncthreads();
    mma_stage(f, Ah, Al, Wh, Wl, wm, wn, lane);

    if (x2) {
        __syncthreads();
        load_A_conv(Ah, Al, x2, m0, tid);
        load_W_pre(Wh, Wl, w1, tid);
        __syncthreads();
        mma_stage(f, Ah, Al, Wh, Wl, wm, wn, lane);
    }

    #pragma unroll
    for (int mt = 0; mt < 2; mt++) {
        #pragma unroll
        for (int half = 0; half < 2; half++) {
            int m = m0 + wm + mt * 16 + g + half * 8;
            if (m >= NN) continue;
            float dv = (flags & FL_DINV) ? g_dinv[m] : 1.f;
            #pragma unroll
            for (int nt = 0; nt < 8; nt++) {
                int col = wn + nt * 8 + 2 * tig;
                float vx = f.c[mt][nt][half * 2 + 0];
                float vy = f.c[mt][nt][half * 2 + 1];
                if (bias) {
                    float2 b2 = __ldg((const float2*)&bias[col]);
                    vx += b2.x; vy += b2.y;
                }
                if (flags & FL_DINV) { vx *= dv; vy *= dv; }
                if (flags & FL_RELU) { vx = fmaxf(vx, 0.f); vy = fmaxf(vy, 0.f); }
                if (flags & FL_OUTBF) {
                    __nv_bfloat16 h0 = __float2bfloat16(vx);
                    __nv_bfloat16 h1 = __float2bfloat16(vy);
                    __nv_bfloat162 hv; hv.x = h0; hv.y = h1;
                    __nv_bfloat162 lv;
                    lv.x = __float2bfloat16(vx - __bfloat162float(h0));
                    lv.y = __float2bfloat16(vy - __bfloat162float(h1));
                    *(__nv_bfloat162*)&outH[(size_t)m * HH + col] = hv;
                    *(__nv_bfloat162*)&outL[(size_t)m * HH + col] = lv;
                } else {
                    float2 r2; r2.x = vx; r2.y = vy;
                    *(float2*)&outF[(size_t)m * HH + col] = r2;
                }
            }
        }
    }
}

// ---------------- pooling + fused finalize ----------------
__global__ void k_pool2(const int* __restrict__ batch) {
    const float* h = g_bufB;
    int c = threadIdx.x;
    int n0 = blockIdx.x * 64;
    int n1 = n0 + 64; if (n1 > NN) n1 = NN;
    if (n0 >= NN) return;
    float acc = 0.f;
    int cur = __ldg(&batch[n0]);
    for (int n = n0; n < n1; n++) {
        int b = __ldg(&batch[n]);
        if (b != cur) { atomicAdd(&g_pool[cur * HH + c], acc); acc = 0.f; cur = b; }
        acc += h[(size_t)n * HH + c];
    }
    atomicAdd(&g_pool[cur * HH + c], acc);
}

__global__ void k_final(const float* __restrict__ Wl, const float* __restrict__ bl,
                        float* __restrict__ dout) {
    __shared__ float ws[4];
    __shared__ float xs[HH];
    __shared__ float winv[CC];
    int g = blockIdx.x, t = threadIdx.x;
    float c = fmaxf(g_cnt[g], 1.f);
    float v = g_pool[g * HH + t] / c;
    float s = v * v;
    #pragma unroll
    for (int o = 16; o > 0; o >>= 1) s += __shfl_down_sync(0xFFFFFFFFu, s, o);
    if ((t & 31) == 0) ws[t >> 5] = s;
    if (t < CC) {
        float sw = 0.f;
        #pragma unroll 8
        for (int k = 0; k < HH; k++) { float w = __ldg(&Wl[t * HH + k]); sw = fmaf(w, w, sw); }
        winv[t] = 1.f / fmaxf(sqrtf(sw), 1e-12f);
    }
    __syncthreads();
    float tot = ws[0] + ws[1] + ws[2] + ws[3];
    float nrm = fmaxf(sqrtf(tot), 1e-12f);
    float xn = v / nrm;
    dout[g * HH + t] = xn;
    xs[t] = xn;
    __syncthreads();
    if (t < CC) {
        float s2 = 0.f;
        #pragma unroll 8
        for (int k = 0; k < HH; k++) s2 = fmaf(xs[k], __ldg(&Wl[t * HH + k]), s2);
        dout[GG * HH + g * CC + t] = fmaf(s2, winv[t], bl[t]);
    }
}

// ---------------- launch ----------------
extern "C" void kernel_launch(void* const* d_in, const int* in_sizes, int n_in,
                              void* d_out, int out_size) {
    const float* x    = (const float*)d_in[0];
    const int*   ei   = (const int*)d_in[1];
    const int*   batch= (const int*)d_in[2];
    const float* W1r  = (const float*)d_in[3];
    const float* b1   = (const float*)d_in[4];
    const float* W1x  = (const float*)d_in[5];
    const float* W2   = (const float*)d_in[6];
    const float* b2   = (const float*)d_in[7];
    const float* W3   = (const float*)d_in[8];
    const float* b3   = (const float*)d_in[9];
    const float* Wl   = (const float*)d_in[10];
    const float* bl   = (const float*)d_in[11];
    const int* row = ei;
    const int* col = ei + EE;
    float* out = (float*)d_out;

    cudaFuncSetAttribute(k_gemm, cudaFuncAttributeMaxDynamicSharedMemorySize, GEMM_SMEM);

    __nv_bfloat16 *aH, *aL, *bH, *bL;
    cudaGetSymbolAddress((void**)&aH, g_aH);
    cudaGetSymbolAddress((void**)&aL, g_aL);
    cudaGetSymbolAddress((void**)&bH, g_bH);
    cudaGetSymbolAddress((void**)&bL, g_bL);
    float *bufA;
    cudaGetSymbolAddress((void**)&bufA, g_bufA);

    // CSR build + degree norm (+ graph counts) + weight conversion
    k_zero<<<(NN + 255) / 256, 256>>>();
    k_deg<<<(EE + 255) / 256, 256>>>(col);
    k_convW<<<(HH * HH + 255) / 256, 256>>>(W1r, W1x, W2, W3);
    k_part<<<SCAN_BLK, 1024>>>();
    k_scanpart<<<1, 64>>>();
    k_addoff<<<SCAN_BLK, 1024>>>();
    k_dinv_cnt<<<(NN + 255) / 256, 256>>>(batch);
    k_fill<<<(EE + 255) / 256, 256>>>(row, col);

    int AGG_GRID = (NN + 7) / 8;
    int GB = (NN + 127) / 128;

    // conv1 (fused): h1 = relu(agg@W1r^T + x@W1x^T + b1) -> split bf16 (bH/bL)
    k_agg1<<<AGG_GRID, 256>>>((const float4*)x);
    k_gemm<<<GB, 256, GEMM_SMEM>>>(aH, aL, 0, x, 1, b1, FL_RELU | FL_OUTBF,
                                   nullptr, bH, bL);

    // conv2: hq2 = (h1@W2^T)*dinv -> fp32 bufA; h2 = relu(dinv*(sum)+b2) -> aH/aL
    k_gemm<<<GB, 256, GEMM_SMEM>>>(bH, bL, 2, nullptr, 0, nullptr, FL_DINV,
                                   bufA, nullptr, nullptr);
    k_aggn<<<AGG_GRID, 256>>>(b2, 1, 1);

    // conv3: hq3 = (h2@W3^T)*dinv -> bufA; h3 = dinv*(sum)+b3 -> fp32 bufB
    k_gemm<<<GB, 256, GEMM_SMEM>>>(aH, aL, 3, nullptr, 0, nullptr, FL_DINV,
                                   bufA, nullptr, nullptr);
    k_aggn<<<AGG_GRID, 256>>>(b3, 0, 0);

    // pooling + normalize + classifier
    k_pool2<<<(NN + 63) / 64, 128>>>(batch);
    k_final<<<GG, HH>>>(Wl, bl, out);
}